// round 1
// baseline (speedup 1.0000x reference)
#include <cuda_runtime.h>

// MySoftBCELoss: B=524288, C=64, f32 logits/target -> scalar f32.
// per_sample = t[l]*log(clip(sigmoid(x[l]))) + log(1 - clip(sigmoid(x[0]))), l = argmax(target_row)
// out = -mean(per_sample)

static constexpr int B_ROWS = 524288;
static constexpr int C_COLS = 64;
static constexpr int ROWS_PER_WARP = 4;
static constexpr int THREADS = 256;
static constexpr int WARPS_PER_BLOCK = THREADS / 32;
static constexpr int ROWS_PER_BLOCK = WARPS_PER_BLOCK * ROWS_PER_WARP;   // 32
static constexpr int GRID = B_ROWS / ROWS_PER_BLOCK;                     // 16384

__device__ double g_accum;

__global__ void zero_accum_kernel() { g_accum = 0.0; }

__global__ __launch_bounds__(THREADS)
void softbce_kernel(const float* __restrict__ logits,
                    const float* __restrict__ target) {
    const int lane = threadIdx.x & 31;
    const int wid  = threadIdx.x >> 5;
    const long long row0 =
        (long long)(blockIdx.x * WARPS_PER_BLOCK + wid) * ROWS_PER_WARP;

    // ---- Load 4 target rows, coalesced: each lane gets float2 of its row ----
    float2 v[ROWS_PER_WARP];
#pragma unroll
    for (int k = 0; k < ROWS_PER_WARP; k++) {
        v[k] = *reinterpret_cast<const float2*>(
            target + (row0 + k) * C_COLS + lane * 2);
    }

    // ---- Per-row argmax (first-max-index semantics) via REDUX on float bits ----
    // target values are in [0,1) (and exactly 0.0 at col 0), so positive-float
    // bit patterns compare in the same order as the values.
    float my_maxv = 0.0f;
    int   my_maxi = 0;
#pragma unroll
    for (int k = 0; k < ROWS_PER_WARP; k++) {
        float val; int idx;
        if (v[k].y > v[k].x) { val = v[k].y; idx = lane * 2 + 1; }
        else                 { val = v[k].x; idx = lane * 2;     }
        unsigned bits = __float_as_uint(val);
        unsigned mx   = __reduce_max_sync(0xffffffffu, bits);
        unsigned ball = __ballot_sync(0xffffffffu, bits == mx);
        int src       = __ffs(ball) - 1;           // lowest lane -> lowest index
        int widx      = __shfl_sync(0xffffffffu, idx, src);
        if (lane == k) { my_maxv = __uint_as_float(mx); my_maxi = widx; }
    }

    // ---- Lanes 0..3 each finalize one row: gather 2 logits, compute term ----
    float partial = 0.0f;
    if (lane < ROWS_PER_WARP) {
        const float* rowp = logits + (row0 + lane) * C_COLS;
        float xl = __ldg(rowp + my_maxi);
        float x0 = __ldg(rowp);
        // p_l = clip(sigmoid(xl)); q0 = 1 - clip(sigmoid(x0)) = clip(sigmoid(-x0))
        float pl = 1.0f / (1.0f + __expf(-xl));
        pl = fminf(fmaxf(pl, 1e-7f), 1.0f - 1e-7f);
        float q0 = 1.0f / (1.0f + __expf(x0));
        q0 = fminf(fmaxf(q0, 1e-7f), 1.0f - 1e-7f);
        partial = my_maxv * __logf(pl) + __logf(q0);
    }

    // ---- Block reduction: shared float (32 adds), then one double atomic ----
    __shared__ float s_sum;
    if (threadIdx.x == 0) s_sum = 0.0f;
    __syncthreads();
    if (lane < ROWS_PER_WARP) atomicAdd(&s_sum, partial);
    __syncthreads();
    if (threadIdx.x == 0) atomicAdd(&g_accum, (double)s_sum);
}

__global__ void finalize_kernel(float* __restrict__ out) {
    out[0] = (float)(-g_accum / (double)B_ROWS);
}

extern "C" void kernel_launch(void* const* d_in, const int* in_sizes, int n_in,
                              void* d_out, int out_size) {
    const float* logits = (const float*)d_in[0];
    const float* target = (const float*)d_in[1];
    float* out = (float*)d_out;

    zero_accum_kernel<<<1, 1>>>();
    softbce_kernel<<<GRID, THREADS>>>(logits, target);
    finalize_kernel<<<1, 1>>>(out);
}

// round 2
// speedup vs baseline: 1.3776x; 1.3776x over previous
#include <cuda_runtime.h>

// MySoftBCELoss: B=524288, C=64, f32 logits/target -> scalar f32.
// l = argmax(target_row) ; per_sample = t[l]*log(clip(sig(x[l]))) + log(clip(sig(-x[0])))
// out = -mean(per_sample)

static constexpr int B_ROWS = 524288;
static constexpr int C_COLS = 64;
static constexpr int ROWS_PER_WARP = 8;
static constexpr int THREADS = 256;
static constexpr int WARPS_PER_BLOCK = THREADS / 32;                 // 8
static constexpr int ROWS_PER_BLOCK = WARPS_PER_BLOCK * ROWS_PER_WARP; // 64
static constexpr int GRID = B_ROWS / ROWS_PER_BLOCK;                 // 8192

__device__ double   g_accum;   // zero-initialized at module load; reset by last block
__device__ unsigned g_count;

__global__ __launch_bounds__(THREADS)
void softbce_fused_kernel(const float* __restrict__ logits,
                          const float* __restrict__ target,
                          float* __restrict__ out) {
    const int lane = threadIdx.x & 31;
    const int wid  = threadIdx.x >> 5;
    const long long row0 =
        (long long)(blockIdx.x * WARPS_PER_BLOCK + wid) * ROWS_PER_WARP;

    // ---- Front-batched loads: 8 target rows, each warp-coalesced 256B ----
    float2 v[ROWS_PER_WARP];
#pragma unroll
    for (int k = 0; k < ROWS_PER_WARP; k++) {
        v[k] = *reinterpret_cast<const float2*>(
            target + (row0 + k) * C_COLS + lane * 2);
    }

    // ---- Argmax: ONE REDUX per row on a packed key ----
    // target in [0,1) -> positive float bits order == value order.
    // key = (bits & ~0x3F) | (63 - idx): max key == max value (to 26-bit
    // precision), ties broken toward the SMALLEST index (first occurrence),
    // matching jnp.argmax. Value error from truncation <= 2^-18 relative.
    unsigned my_key = 0;
#pragma unroll
    for (int k = 0; k < ROWS_PER_WARP; k++) {
        unsigned kx = (__float_as_uint(v[k].x) & 0xFFFFFFC0u) | (unsigned)(63 - 2 * lane);
        unsigned ky = (__float_as_uint(v[k].y) & 0xFFFFFFC0u) | (unsigned)(62 - 2 * lane);
        unsigned loc = kx > ky ? kx : ky;
        unsigned mx  = __reduce_max_sync(0xffffffffu, loc);
        if (lane == k) my_key = mx;
    }

    // ---- Lanes 0..7 finalize one row each ----
    float partial = 0.0f;
    if (lane < ROWS_PER_WARP) {
        int   idx  = 63 - (int)(my_key & 63u);
        float tval = __uint_as_float(my_key & 0xFFFFFFC0u);
        const float* rowp = logits + (row0 + lane) * C_COLS;
        float xl = __ldg(rowp + idx);
        float x0 = __ldg(rowp);
        float pl = 1.0f / (1.0f + __expf(-xl));     // sigmoid(xl)
        pl = fminf(fmaxf(pl, 1e-7f), 1.0f - 1e-7f);
        float q0 = 1.0f / (1.0f + __expf(x0));      // 1 - sigmoid(x0)
        q0 = fminf(fmaxf(q0, 1e-7f), 1.0f - 1e-7f);
        partial = tval * __logf(pl) + __logf(q0);
    }

    // ---- Warp tree-reduce lanes 0..7, then shared, then one REDG/block ----
    partial += __shfl_down_sync(0xffffffffu, partial, 4);
    partial += __shfl_down_sync(0xffffffffu, partial, 2);
    partial += __shfl_down_sync(0xffffffffu, partial, 1);

    __shared__ float s_sum;
    if (threadIdx.x == 0) s_sum = 0.0f;
    __syncthreads();
    if (lane == 0) atomicAdd(&s_sum, partial);
    __syncthreads();

    // ---- Last-block finalize (single-kernel, graph-replay-safe) ----
    __shared__ bool is_last;
    if (threadIdx.x == 0) {
        atomicAdd(&g_accum, (double)s_sum);
        __threadfence();
        unsigned ticket = atomicAdd(&g_count, 1u);
        is_last = (ticket == (unsigned)(GRID - 1));
    }
    __syncthreads();
    if (is_last && threadIdx.x == 0) {
        __threadfence();
        double total = atomicAdd(&g_accum, 0.0);    // coherent L2 read
        out[0] = (float)(-total / (double)B_ROWS);
        g_accum = 0.0;                              // reset for next replay
        g_count = 0u;
    }
}

extern "C" void kernel_launch(void* const* d_in, const int* in_sizes, int n_in,
                              void* d_out, int out_size) {
    const float* logits = (const float*)d_in[0];
    const float* target = (const float*)d_in[1];
    float* out = (float*)d_out;
    softbce_fused_kernel<<<GRID, THREADS>>>(logits, target, out);
}

// round 3
// speedup vs baseline: 1.4012x; 1.0172x over previous
#include <cuda_runtime.h>

// MySoftBCELoss: B=524288, C=64, f32 -> scalar f32.
// l = argmax(target_row); per_sample = t[l]*log(clip(sig(x[l]))) + log(clip(sig(-x[0])))
// out = -mean(per_sample)
// Persistent double-buffered streaming kernel: 592 CTAs (4/SM exactly).

static constexpr int B_ROWS        = 524288;
static constexpr int C_COLS        = 64;
static constexpr int ROWS_PER_TILE = 8;                         // rows per warp per iter
static constexpr int NTILES        = B_ROWS / ROWS_PER_TILE;    // 65536
static constexpr int THREADS       = 256;
static constexpr int WARPS_PER_BLOCK = THREADS / 32;            // 8
static constexpr int GRID          = 592;                       // 4 CTAs x 148 SMs
static constexpr int TOTAL_WARPS   = GRID * WARPS_PER_BLOCK;    // 4736

__device__ double   g_accum;    // zero at module load; reset by last block each replay
__device__ unsigned g_count;

__device__ __forceinline__ void load_tile(const float* __restrict__ target,
                                          const float* __restrict__ logits,
                                          int tile, int lane,
                                          float2 (&v)[ROWS_PER_TILE], float& x0) {
    const float* tp = target + (long long)tile * (ROWS_PER_TILE * C_COLS) + lane * 2;
#pragma unroll
    for (int k = 0; k < ROWS_PER_TILE; k++)
        v[k] = *reinterpret_cast<const float2*>(tp + k * C_COLS);
    // x0 prefetch (independent of argmax): lane r owns row r of this tile
    if (lane < ROWS_PER_TILE)
        x0 = __ldg(logits + ((long long)tile * ROWS_PER_TILE + lane) * C_COLS);
}

__device__ __forceinline__ float process_tile(const float* __restrict__ logits,
                                              int tile, int lane,
                                              const float2 (&v)[ROWS_PER_TILE],
                                              float x0) {
    // Argmax via ONE REDUX per row on packed key:
    // target in [0,1) -> positive float bits order == value order.
    // key = (bits & ~0x3F) | (63 - idx): ties break to smallest idx (jnp.argmax),
    // value truncation error <= 2^-18 relative.
    unsigned my_key = 0;
#pragma unroll
    for (int k = 0; k < ROWS_PER_TILE; k++) {
        unsigned kx = (__float_as_uint(v[k].x) & 0xFFFFFFC0u) | (unsigned)(63 - 2 * lane);
        unsigned ky = (__float_as_uint(v[k].y) & 0xFFFFFFC0u) | (unsigned)(62 - 2 * lane);
        unsigned loc = kx > ky ? kx : ky;
        unsigned mx  = __reduce_max_sync(0xffffffffu, loc);
        if (lane == k) my_key = mx;
    }
    float term = 0.0f;
    if (lane < ROWS_PER_TILE) {
        int   idx  = 63 - (int)(my_key & 63u);
        float tval = __uint_as_float(my_key & 0xFFFFFFC0u);
        float xl = __ldg(logits + ((long long)tile * ROWS_PER_TILE + lane) * C_COLS + idx);
        float pl = 1.0f / (1.0f + __expf(-xl));           // sigmoid(xl)
        pl = fminf(fmaxf(pl, 1e-7f), 1.0f - 1e-7f);
        float q0 = 1.0f / (1.0f + __expf(x0));            // 1 - sigmoid(x0)
        q0 = fminf(fmaxf(q0, 1e-7f), 1.0f - 1e-7f);
        term = tval * __logf(pl) + __logf(q0);
    }
    return term;
}

__global__ __launch_bounds__(THREADS, 4)
void softbce_persistent_kernel(const float* __restrict__ logits,
                               const float* __restrict__ target,
                               float* __restrict__ out) {
    const int lane = threadIdx.x & 31;
    const int wid  = threadIdx.x >> 5;
    const int gw   = blockIdx.x * WARPS_PER_BLOCK + wid;

    float partial = 0.0f;

    // ---- Software-pipelined grid-stride loop over warp-tiles ----
    float2 va[ROWS_PER_TILE];
    float  x0a = 0.0f;
    int tile = gw;
    if (tile < NTILES) load_tile(target, logits, tile, lane, va, x0a);
    while (tile < NTILES) {
        const int nt = tile + TOTAL_WARPS;
        float2 vb[ROWS_PER_TILE];
        float  x0b = 0.0f;
        if (nt < NTILES) load_tile(target, logits, nt, lane, vb, x0b);  // overlap
        partial += process_tile(logits, tile, lane, va, x0a);
        tile = nt;
#pragma unroll
        for (int k = 0; k < ROWS_PER_TILE; k++) va[k] = vb[k];
        x0a = x0b;
    }

    // ---- One block reduction total ----
    partial += __shfl_down_sync(0xffffffffu, partial, 16);
    partial += __shfl_down_sync(0xffffffffu, partial, 8);
    partial += __shfl_down_sync(0xffffffffu, partial, 4);
    partial += __shfl_down_sync(0xffffffffu, partial, 2);
    partial += __shfl_down_sync(0xffffffffu, partial, 1);

    __shared__ float s_warp[WARPS_PER_BLOCK];
    if (lane == 0) s_warp[wid] = partial;
    __syncthreads();

    if (wid == 0) {
        float s = (lane < WARPS_PER_BLOCK) ? s_warp[lane] : 0.0f;
        s += __shfl_down_sync(0xffffffffu, s, 4);
        s += __shfl_down_sync(0xffffffffu, s, 2);
        s += __shfl_down_sync(0xffffffffu, s, 1);
        if (lane == 0) {
            atomicAdd(&g_accum, (double)s);
            __threadfence();
            unsigned ticket = atomicAdd(&g_count, 1u);
            if (ticket == (unsigned)(GRID - 1)) {
                __threadfence();
                double total = atomicAdd(&g_accum, 0.0);   // coherent read
                out[0] = (float)(-total / (double)B_ROWS);
                g_accum = 0.0;                              // reset for next replay
                g_count = 0u;
            }
        }
    }
}

extern "C" void kernel_launch(void* const* d_in, const int* in_sizes, int n_in,
                              void* d_out, int out_size) {
    const float* logits = (const float*)d_in[0];
    const float* target = (const float*)d_in[1];
    float* out = (float*)d_out;
    softbce_persistent_kernel<<<GRID, THREADS>>>(logits, target, out);
}